// round 7
// baseline (speedup 1.0000x reference)
#include <cuda_runtime.h>
#include <cstdint>

#define D 128
#define NMAX 50000
#define EMAX 600000
#define SCAN_B 1024
#define NBMAX 64

// allocation-free scratch
__device__ int g_deg[NMAX];
__device__ int g_off[NMAX + 1];
__device__ int g_cur[NMAX];
__device__ int g_eid[EMAX];
__device__ int g_part[NBMAX];

// ============================ CSR build =====================================
__global__ void hist_kernel(const int* __restrict__ dst, int* __restrict__ deg, int E) {
    int e = blockIdx.x * blockDim.x + threadIdx.x;
    if (e < E) atomicAdd(&deg[__ldg(dst + e)], 1);
}

__global__ void __launch_bounds__(SCAN_B)
blocksum_kernel(const int* __restrict__ deg, int* __restrict__ part, int N) {
    __shared__ int red[32];
    int i = blockIdx.x * SCAN_B + threadIdx.x;
    int v = (i < N) ? deg[i] : 0;
    #pragma unroll
    for (int o = 16; o > 0; o >>= 1) v += __shfl_down_sync(0xffffffffu, v, o);
    if ((threadIdx.x & 31) == 0) red[threadIdx.x >> 5] = v;
    __syncthreads();
    if (threadIdx.x < 32) {
        int s = red[threadIdx.x];
        #pragma unroll
        for (int o = 16; o > 0; o >>= 1) s += __shfl_down_sync(0xffffffffu, s, o);
        if (threadIdx.x == 0) part[blockIdx.x] = s;
    }
}

__global__ void scanpart_kernel(int* __restrict__ part, int nb) {
    int t = threadIdx.x;
    int v = (t < nb) ? part[t] : 0;
    int lane = t & 31, w = t >> 5;
    int inc = v;
    #pragma unroll
    for (int o = 1; o < 32; o <<= 1) {
        int u = __shfl_up_sync(0xffffffffu, inc, o);
        if (lane >= o) inc += u;
    }
    __shared__ int ws[2];
    if (lane == 31) ws[w] = inc;
    __syncthreads();
    if (w == 1) inc += ws[0];
    if (t < nb) part[t] = inc - v;
}

__global__ void __launch_bounds__(SCAN_B)
scatter_kernel(const int* __restrict__ deg, const int* __restrict__ part,
               int* __restrict__ off, int* __restrict__ cur, int N) {
    __shared__ int wsum[32];
    int i = blockIdx.x * SCAN_B + threadIdx.x;
    int v = (i < N) ? deg[i] : 0;
    int lane = threadIdx.x & 31, w = threadIdx.x >> 5;
    int inc = v;
    #pragma unroll
    for (int o = 1; o < 32; o <<= 1) {
        int u = __shfl_up_sync(0xffffffffu, inc, o);
        if (lane >= o) inc += u;
    }
    if (lane == 31) wsum[w] = inc;
    __syncthreads();
    if (w == 0) {
        int s = wsum[lane];
        int si = s;
        #pragma unroll
        for (int o = 1; o < 32; o <<= 1) {
            int u = __shfl_up_sync(0xffffffffu, si, o);
            if (lane >= o) si += u;
        }
        wsum[lane] = si - s;
    }
    __syncthreads();
    int excl = part[blockIdx.x] + wsum[w] + (inc - v);
    if (i < N) {
        off[i] = excl;
        cur[i] = excl;
        if (i == N - 1) off[N] = excl + v;
    }
}

__global__ void fill_kernel(const int* __restrict__ dst, int* __restrict__ cur,
                            int* __restrict__ eid, int E) {
    int e = blockIdx.x * blockDim.x + threadIdx.x;
    if (e < E) {
        int pos = atomicAdd(&cur[__ldg(dst + e)], 1);
        eid[pos] = e;
    }
}

// ===================== fused gather + TF32 GEMM =============================
// Block = 64 node-rows. Each of 8 warps gathers 8 rows:
//   aggRow = h[n] * sum_{e in bucket(n)} e_h[e]   (tf32-rounded into smem)
// Then MMA: out[n][j] = (sum_k aggRow[k] * W[j][k] + b[j]) * norm[n]
#define MB 64
#define LDP 132
#define SM_WORDS (MB * LDP + 128 * LDP)
#define SM_BYTES (SM_WORDS * 4)

__device__ __forceinline__ uint32_t f2tf32(float x) {
    uint32_t r;
    asm("cvt.rna.tf32.f32 %0, %1;" : "=r"(r) : "f"(x));
    return r;
}

__device__ __forceinline__ void mma_tf32(float* c, const uint32_t* a, const uint32_t* bb) {
    asm volatile(
        "mma.sync.aligned.m16n8k8.row.col.f32.tf32.tf32.f32 "
        "{%0,%1,%2,%3}, {%4,%5,%6,%7}, {%8,%9}, {%0,%1,%2,%3};"
        : "+f"(c[0]), "+f"(c[1]), "+f"(c[2]), "+f"(c[3])
        : "r"(a[0]), "r"(a[1]), "r"(a[2]), "r"(a[3]), "r"(bb[0]), "r"(bb[1]));
}

__global__ void __launch_bounds__(256, 2)
fused_kernel(const float* __restrict__ h,
             const float* __restrict__ e_h,
             const int* __restrict__ off,
             const int* __restrict__ eid,
             const float* __restrict__ W,
             const float* __restrict__ b,
             const float* __restrict__ norm,
             float* __restrict__ out,
             int N) {
    extern __shared__ uint32_t sm[];
    uint32_t* As = sm;               // [MB][LDP]
    uint32_t* Ws = sm + MB * LDP;    // [128][LDP]

    const int tid  = threadIdx.x;
    const int wid  = tid >> 5;
    const int lane = tid & 31;
    const int rowBase = blockIdx.x * MB;

    // ---- stage W tile (tf32) : 128 rows x 32 float4, 16 float4/thread ----
    #pragma unroll
    for (int t = 0; t < 16; t++) {
        int idx = tid + t * 256;
        int row = idx >> 5;
        int c4  = idx & 31;
        float4 v = ((const float4*)(W + (size_t)row * D))[c4];
        uint4 tv;
        tv.x = f2tf32(v.x); tv.y = f2tf32(v.y);
        tv.z = f2tf32(v.z); tv.w = f2tf32(v.w);
        *(uint4*)(Ws + (size_t)row * LDP + c4 * 4) = tv;
    }

    // ---- gather: warp wid handles rows wid*8 .. wid*8+7 ----
    #pragma unroll 1
    for (int rr = 0; rr < 8; rr++) {
        int r = wid * 8 + rr;
        int n = rowBase + r;
        float4 res = make_float4(0.f, 0.f, 0.f, 0.f);
        if (n < N) {
            int s = __ldg(off + n);
            int t = __ldg(off + n + 1);
            float4 a0 = make_float4(0.f, 0.f, 0.f, 0.f);
            float4 a1 = make_float4(0.f, 0.f, 0.f, 0.f);
            float4 a2 = make_float4(0.f, 0.f, 0.f, 0.f);
            float4 a3 = make_float4(0.f, 0.f, 0.f, 0.f);
            int i = s;
            for (; i + 3 < t; i += 4) {
                int e0 = __ldg(eid + i);
                int e1 = __ldg(eid + i + 1);
                int e2 = __ldg(eid + i + 2);
                int e3 = __ldg(eid + i + 3);
                float4 v0 = ((const float4*)(e_h + (size_t)e0 * D))[lane];
                float4 v1 = ((const float4*)(e_h + (size_t)e1 * D))[lane];
                float4 v2 = ((const float4*)(e_h + (size_t)e2 * D))[lane];
                float4 v3 = ((const float4*)(e_h + (size_t)e3 * D))[lane];
                a0.x += v0.x; a0.y += v0.y; a0.z += v0.z; a0.w += v0.w;
                a1.x += v1.x; a1.y += v1.y; a1.z += v1.z; a1.w += v1.w;
                a2.x += v2.x; a2.y += v2.y; a2.z += v2.z; a2.w += v2.w;
                a3.x += v3.x; a3.y += v3.y; a3.z += v3.z; a3.w += v3.w;
            }
            for (; i < t; i++) {
                int e0 = __ldg(eid + i);
                float4 v0 = ((const float4*)(e_h + (size_t)e0 * D))[lane];
                a0.x += v0.x; a0.y += v0.y; a0.z += v0.z; a0.w += v0.w;
            }
            float4 hv = ((const float4*)(h + (size_t)n * D))[lane];
            res.x = (a0.x + a1.x + a2.x + a3.x) * hv.x;
            res.y = (a0.y + a1.y + a2.y + a3.y) * hv.y;
            res.z = (a0.z + a1.z + a2.z + a3.z) * hv.z;
            res.w = (a0.w + a1.w + a2.w + a3.w) * hv.w;
        }
        uint4 tv;
        tv.x = f2tf32(res.x); tv.y = f2tf32(res.y);
        tv.z = f2tf32(res.z); tv.w = f2tf32(res.w);
        *(uint4*)(As + (size_t)r * LDP + lane * 4) = tv;
    }
    __syncthreads();

    // ---- MMA: warp tile 32(M) x 32(N); wid&1 -> M half, wid>>1 -> N quarter
    const int mBase = (wid & 1) * 32;
    const int nBase = (wid >> 1) * 32;
    const int gID = lane >> 2;  // 0..7
    const int tig = lane & 3;   // 0..3

    float acc[8][4];   // [mt*4+nt][4]
    #pragma unroll
    for (int i = 0; i < 8; i++)
        #pragma unroll
        for (int j = 0; j < 4; j++) acc[i][j] = 0.0f;

    #pragma unroll
    for (int ks = 0; ks < 16; ks++) {
        const int k0 = ks * 8;
        uint32_t a[2][4];
        #pragma unroll
        for (int mt = 0; mt < 2; mt++) {
            int r0 = mBase + mt * 16 + gID;
            a[mt][0] = As[(size_t)r0 * LDP + k0 + tig];
            a[mt][1] = As[(size_t)(r0 + 8) * LDP + k0 + tig];
            a[mt][2] = As[(size_t)r0 * LDP + k0 + tig + 4];
            a[mt][3] = As[(size_t)(r0 + 8) * LDP + k0 + tig + 4];
        }
        uint32_t bf[4][2];
        #pragma unroll
        for (int nt = 0; nt < 4; nt++) {
            int nn = nBase + nt * 8 + gID;
            bf[nt][0] = Ws[(size_t)nn * LDP + k0 + tig];
            bf[nt][1] = Ws[(size_t)nn * LDP + k0 + tig + 4];
        }
        #pragma unroll
        for (int mt = 0; mt < 2; mt++)
            #pragma unroll
            for (int nt = 0; nt < 4; nt++)
                mma_tf32(acc[mt * 4 + nt], a[mt], bf[nt]);
    }

    // ---- epilogue: (acc + b) * norm ----
    #pragma unroll
    for (int mt = 0; mt < 2; mt++) {
        #pragma unroll
        for (int half = 0; half < 2; half++) {
            int m = rowBase + mBase + mt * 16 + half * 8 + gID;
            if (m >= N) continue;
            float nm = __ldg(norm + m);
            #pragma unroll
            for (int nt = 0; nt < 4; nt++) {
                int col = nBase + nt * 8 + tig * 2;
                float2 bb = *(const float2*)(b + col);
                float2 r;
                r.x = (acc[mt * 4 + nt][half * 2 + 0] + bb.x) * nm;
                r.y = (acc[mt * 4 + nt][half * 2 + 1] + bb.y) * nm;
                *(float2*)(out + (size_t)m * D + col) = r;
            }
        }
    }
}

// ============================ launch ========================================
extern "C" void kernel_launch(void* const* d_in, const int* in_sizes, int n_in,
                              void* d_out, int out_size) {
    const float* h    = (const float*)d_in[0];
    const float* e_h  = (const float*)d_in[1];
    const float* norm = (const float*)d_in[2];
    const int*   dst  = (const int*)d_in[3];
    const float* W    = (const float*)d_in[4];
    const float* b    = (const float*)d_in[5];
    float*       out  = (float*)d_out;

    const int N = in_sizes[2];
    const int E = in_sizes[3];

    int* deg; int* off; int* cur; int* eid; int* part;
    cudaGetSymbolAddress((void**)&deg, g_deg);
    cudaGetSymbolAddress((void**)&off, g_off);
    cudaGetSymbolAddress((void**)&cur, g_cur);
    cudaGetSymbolAddress((void**)&eid, g_eid);
    cudaGetSymbolAddress((void**)&part, g_part);

    cudaMemsetAsync(deg, 0, (size_t)N * sizeof(int), 0);

    hist_kernel<<<(E + 255) / 256, 256>>>(dst, deg, E);

    int nb = (N + SCAN_B - 1) / SCAN_B;
    blocksum_kernel<<<nb, SCAN_B>>>(deg, part, N);
    scanpart_kernel<<<1, 64>>>(part, nb);
    scatter_kernel<<<nb, SCAN_B>>>(deg, part, off, cur, N);

    fill_kernel<<<(E + 255) / 256, 256>>>(dst, cur, eid, E);

    cudaFuncSetAttribute(fused_kernel,
                         cudaFuncAttributeMaxDynamicSharedMemorySize, SM_BYTES);
    fused_kernel<<<(N + MB - 1) / MB, 256, SM_BYTES>>>(
        h, e_h, off, eid, W, b, norm, out, N);
}

// round 8
// speedup vs baseline: 1.1878x; 1.1878x over previous
#include <cuda_runtime.h>
#include <cstdint>

#define D 128
#define NMAX 50000
#define EMAX 600000
#define SCAN_B 1024
#define NBMAX 64

// allocation-free scratch
__device__ int      g_deg[NMAX];
__device__ int      g_off[NMAX + 1];
__device__ int      g_cur[NMAX];
__device__ int      g_eid[EMAX];
__device__ int      g_part[NBMAX];
__device__ uint32_t g_Wt[D * D];    // W as tf32 bits, row-major [j][k]

// ============================ CSR build =====================================
__global__ void hist_kernel(const int* __restrict__ dst, int* __restrict__ deg, int E) {
    int e = blockIdx.x * blockDim.x + threadIdx.x;
    if (e < E) atomicAdd(&deg[__ldg(dst + e)], 1);
}

__global__ void __launch_bounds__(SCAN_B)
blocksum_kernel(const int* __restrict__ deg, int* __restrict__ part, int N) {
    __shared__ int red[32];
    int i = blockIdx.x * SCAN_B + threadIdx.x;
    int v = (i < N) ? deg[i] : 0;
    #pragma unroll
    for (int o = 16; o > 0; o >>= 1) v += __shfl_down_sync(0xffffffffu, v, o);
    if ((threadIdx.x & 31) == 0) red[threadIdx.x >> 5] = v;
    __syncthreads();
    if (threadIdx.x < 32) {
        int s = red[threadIdx.x];
        #pragma unroll
        for (int o = 16; o > 0; o >>= 1) s += __shfl_down_sync(0xffffffffu, s, o);
        if (threadIdx.x == 0) part[blockIdx.x] = s;
    }
}

__global__ void scanpart_kernel(int* __restrict__ part, int nb) {
    int t = threadIdx.x;
    int v = (t < nb) ? part[t] : 0;
    int lane = t & 31, w = t >> 5;
    int inc = v;
    #pragma unroll
    for (int o = 1; o < 32; o <<= 1) {
        int u = __shfl_up_sync(0xffffffffu, inc, o);
        if (lane >= o) inc += u;
    }
    __shared__ int ws[2];
    if (lane == 31) ws[w] = inc;
    __syncthreads();
    if (w == 1) inc += ws[0];
    if (t < nb) part[t] = inc - v;
}

__global__ void __launch_bounds__(SCAN_B)
scatter_kernel(const int* __restrict__ deg, const int* __restrict__ part,
               int* __restrict__ off, int* __restrict__ cur, int N) {
    __shared__ int wsum[32];
    int i = blockIdx.x * SCAN_B + threadIdx.x;
    int v = (i < N) ? deg[i] : 0;
    int lane = threadIdx.x & 31, w = threadIdx.x >> 5;
    int inc = v;
    #pragma unroll
    for (int o = 1; o < 32; o <<= 1) {
        int u = __shfl_up_sync(0xffffffffu, inc, o);
        if (lane >= o) inc += u;
    }
    if (lane == 31) wsum[w] = inc;
    __syncthreads();
    if (w == 0) {
        int s = wsum[lane];
        int si = s;
        #pragma unroll
        for (int o = 1; o < 32; o <<= 1) {
            int u = __shfl_up_sync(0xffffffffu, si, o);
            if (lane >= o) si += u;
        }
        wsum[lane] = si - s;
    }
    __syncthreads();
    int excl = part[blockIdx.x] + wsum[w] + (inc - v);
    if (i < N) {
        off[i] = excl;
        cur[i] = excl;
        if (i == N - 1) off[N] = excl + v;
    }
}

__global__ void fill_kernel(const int* __restrict__ dst, int* __restrict__ cur,
                            int* __restrict__ eid, int E) {
    int e = blockIdx.x * blockDim.x + threadIdx.x;
    if (e < E) {
        int pos = atomicAdd(&cur[__ldg(dst + e)], 1);
        eid[pos] = e;
    }
}

// ============================ W -> tf32 =====================================
__device__ __forceinline__ uint32_t f2tf32(float x) {
    uint32_t r;
    asm("cvt.rna.tf32.f32 %0, %1;" : "=r"(r) : "f"(x));
    return r;
}

__global__ void wcvt_kernel(const float* __restrict__ W, uint32_t* __restrict__ Wt) {
    int i = blockIdx.x * blockDim.x + threadIdx.x;
    if (i < D * D) Wt[i] = f2tf32(W[i]);
}

// ===================== fused gather + TF32 GEMM =============================
// Block = 64 node-rows, 8 warps, 8 rows/warp.
//   aggRow = h[n] * sum_{e in bucket(n)} e_h[e]  -> tf32 in smem As
//   out[n][j] = (sum_k aggRow[k] * Wt[j][k] + b[j]) * norm[n]
// W fragments come from global tf32 buffer (L1-resident, 64 KB).
#define MB 64
#define LDP 132

__device__ __forceinline__ void mma_tf32(float* c, const uint32_t* a, const uint32_t* bb) {
    asm volatile(
        "mma.sync.aligned.m16n8k8.row.col.f32.tf32.tf32.f32 "
        "{%0,%1,%2,%3}, {%4,%5,%6,%7}, {%8,%9}, {%0,%1,%2,%3};"
        : "+f"(c[0]), "+f"(c[1]), "+f"(c[2]), "+f"(c[3])
        : "r"(a[0]), "r"(a[1]), "r"(a[2]), "r"(a[3]), "r"(bb[0]), "r"(bb[1]));
}

__global__ void __launch_bounds__(256, 3)
fused_kernel(const float* __restrict__ h,
             const float* __restrict__ e_h,
             const int* __restrict__ off,
             const int* __restrict__ eid,
             const uint32_t* __restrict__ Wt,
             const float* __restrict__ b,
             const float* __restrict__ norm,
             float* __restrict__ out,
             int N) {
    __shared__ uint32_t As[MB * LDP];

    const int tid  = threadIdx.x;
    const int wid  = tid >> 5;
    const int lane = tid & 31;
    const int rowBase = blockIdx.x * MB;

    // ---- gather: warp wid handles rows wid*8 .. wid*8+7; 8-deep edge MLP ----
    #pragma unroll 1
    for (int rr = 0; rr < 8; rr++) {
        int r = wid * 8 + rr;
        int n = rowBase + r;
        float4 res = make_float4(0.f, 0.f, 0.f, 0.f);
        if (n < N) {
            int s = __ldg(off + n);
            int t = __ldg(off + n + 1);
            float4 a0 = make_float4(0.f, 0.f, 0.f, 0.f);
            float4 a1 = make_float4(0.f, 0.f, 0.f, 0.f);
            float4 a2 = make_float4(0.f, 0.f, 0.f, 0.f);
            float4 a3 = make_float4(0.f, 0.f, 0.f, 0.f);
            int i = s;
            for (; i + 7 < t; i += 8) {
                int e0 = __ldg(eid + i);
                int e1 = __ldg(eid + i + 1);
                int e2 = __ldg(eid + i + 2);
                int e3 = __ldg(eid + i + 3);
                int e4 = __ldg(eid + i + 4);
                int e5 = __ldg(eid + i + 5);
                int e6 = __ldg(eid + i + 6);
                int e7 = __ldg(eid + i + 7);
                float4 v0 = ((const float4*)(e_h + (size_t)e0 * D))[lane];
                float4 v1 = ((const float4*)(e_h + (size_t)e1 * D))[lane];
                float4 v2 = ((const float4*)(e_h + (size_t)e2 * D))[lane];
                float4 v3 = ((const float4*)(e_h + (size_t)e3 * D))[lane];
                float4 v4 = ((const float4*)(e_h + (size_t)e4 * D))[lane];
                float4 v5 = ((const float4*)(e_h + (size_t)e5 * D))[lane];
                float4 v6 = ((const float4*)(e_h + (size_t)e6 * D))[lane];
                float4 v7 = ((const float4*)(e_h + (size_t)e7 * D))[lane];
                a0.x += v0.x; a0.y += v0.y; a0.z += v0.z; a0.w += v0.w;
                a1.x += v1.x; a1.y += v1.y; a1.z += v1.z; a1.w += v1.w;
                a2.x += v2.x; a2.y += v2.y; a2.z += v2.z; a2.w += v2.w;
                a3.x += v3.x; a3.y += v3.y; a3.z += v3.z; a3.w += v3.w;
                a0.x += v4.x; a0.y += v4.y; a0.z += v4.z; a0.w += v4.w;
                a1.x += v5.x; a1.y += v5.y; a1.z += v5.z; a1.w += v5.w;
                a2.x += v6.x; a2.y += v6.y; a2.z += v6.z; a2.w += v6.w;
                a3.x += v7.x; a3.y += v7.y; a3.z += v7.z; a3.w += v7.w;
            }
            for (; i + 3 < t; i += 4) {
                int e0 = __ldg(eid + i);
                int e1 = __ldg(eid + i + 1);
                int e2 = __ldg(eid + i + 2);
                int e3 = __ldg(eid + i + 3);
                float4 v0 = ((const float4*)(e_h + (size_t)e0 * D))[lane];
                float4 v1 = ((const float4*)(e_h + (size_t)e1 * D))[lane];
                float4 v2 = ((const float4*)(e_h + (size_t)e2 * D))[lane];
                float4 v3 = ((const float4*)(e_h + (size_t)e3 * D))[lane];
                a0.x += v0.x; a0.y += v0.y; a0.z += v0.z; a0.w += v0.w;
                a1.x += v1.x; a1.y += v1.y; a1.z += v1.z; a1.w += v1.w;
                a2.x += v2.x; a2.y += v2.y; a2.z += v2.z; a2.w += v2.w;
                a3.x += v3.x; a3.y += v3.y; a3.z += v3.z; a3.w += v3.w;
            }
            for (; i < t; i++) {
                int e0 = __ldg(eid + i);
                float4 v0 = ((const float4*)(e_h + (size_t)e0 * D))[lane];
                a0.x += v0.x; a0.y += v0.y; a0.z += v0.z; a0.w += v0.w;
            }
            float4 hv = ((const float4*)(h + (size_t)n * D))[lane];
            res.x = (a0.x + a1.x + a2.x + a3.x) * hv.x;
            res.y = (a0.y + a1.y + a2.y + a3.y) * hv.y;
            res.z = (a0.z + a1.z + a2.z + a3.z) * hv.z;
            res.w = (a0.w + a1.w + a2.w + a3.w) * hv.w;
        }
        uint4 tv;
        tv.x = f2tf32(res.x); tv.y = f2tf32(res.y);
        tv.z = f2tf32(res.z); tv.w = f2tf32(res.w);
        *(uint4*)(As + (size_t)r * LDP + lane * 4) = tv;
    }
    __syncthreads();

    // ---- MMA: warp tile 32(M) x 32(N); wid&1 -> M half, wid>>1 -> N quarter
    const int mBase = (wid & 1) * 32;
    const int nBase = (wid >> 1) * 32;
    const int gID = lane >> 2;  // 0..7
    const int tig = lane & 3;   // 0..3

    float acc[8][4];
    #pragma unroll
    for (int i = 0; i < 8; i++)
        #pragma unroll
        for (int j = 0; j < 4; j++) acc[i][j] = 0.0f;

    #pragma unroll
    for (int ks = 0; ks < 16; ks++) {
        const int k0 = ks * 8;
        uint32_t a[2][4];
        #pragma unroll
        for (int mt = 0; mt < 2; mt++) {
            int r0 = mBase + mt * 16 + gID;
            a[mt][0] = As[(size_t)r0 * LDP + k0 + tig];
            a[mt][1] = As[(size_t)(r0 + 8) * LDP + k0 + tig];
            a[mt][2] = As[(size_t)r0 * LDP + k0 + tig + 4];
            a[mt][3] = As[(size_t)(r0 + 8) * LDP + k0 + tig + 4];
        }
        uint32_t bf[4][2];
        #pragma unroll
        for (int nt = 0; nt < 4; nt++) {
            int nn = nBase + nt * 8 + gID;
            bf[nt][0] = __ldg(Wt + (size_t)nn * D + k0 + tig);
            bf[nt][1] = __ldg(Wt + (size_t)nn * D + k0 + tig + 4);
        }
        #pragma unroll
        for (int mt = 0; mt < 2; mt++)
            #pragma unroll
            for (int nt = 0; nt < 4; nt++)
                mma_tf32(acc[mt * 4 + nt], a[mt], bf[nt]);
    }

    // ---- epilogue: (acc + b) * norm ----
    #pragma unroll
    for (int mt = 0; mt < 2; mt++) {
        #pragma unroll
        for (int half = 0; half < 2; half++) {
            int m = rowBase + mBase + mt * 16 + half * 8 + gID;
            if (m >= N) continue;
            float nm = __ldg(norm + m);
            #pragma unroll
            for (int nt = 0; nt < 4; nt++) {
                int col = nBase + nt * 8 + tig * 2;
                float2 bb = *(const float2*)(b + col);
                float2 r;
                r.x = (acc[mt * 4 + nt][half * 2 + 0] + bb.x) * nm;
                r.y = (acc[mt * 4 + nt][half * 2 + 1] + bb.y) * nm;
                *(float2*)(out + (size_t)m * D + col) = r;
            }
        }
    }
}

// ============================ launch ========================================
extern "C" void kernel_launch(void* const* d_in, const int* in_sizes, int n_in,
                              void* d_out, int out_size) {
    const float* h    = (const float*)d_in[0];
    const float* e_h  = (const float*)d_in[1];
    const float* norm = (const float*)d_in[2];
    const int*   dst  = (const int*)d_in[3];
    const float* W    = (const float*)d_in[4];
    const float* b    = (const float*)d_in[5];
    float*       out  = (float*)d_out;

    const int N = in_sizes[2];
    const int E = in_sizes[3];

    int* deg; int* off; int* cur; int* eid; int* part; uint32_t* Wt;
    cudaGetSymbolAddress((void**)&deg, g_deg);
    cudaGetSymbolAddress((void**)&off, g_off);
    cudaGetSymbolAddress((void**)&cur, g_cur);
    cudaGetSymbolAddress((void**)&eid, g_eid);
    cudaGetSymbolAddress((void**)&part, g_part);
    cudaGetSymbolAddress((void**)&Wt, g_Wt);

    cudaMemsetAsync(deg, 0, (size_t)N * sizeof(int), 0);

    wcvt_kernel<<<(D * D + 255) / 256, 256>>>(W, Wt);
    hist_kernel<<<(E + 255) / 256, 256>>>(dst, deg, E);

    int nb = (N + SCAN_B - 1) / SCAN_B;
    blocksum_kernel<<<nb, SCAN_B>>>(deg, part, N);
    scanpart_kernel<<<1, 64>>>(part, nb);
    scatter_kernel<<<nb, SCAN_B>>>(deg, part, off, cur, N);

    fill_kernel<<<(E + 255) / 256, 256>>>(dst, cur, eid, E);

    fused_kernel<<<(N + MB - 1) / MB, 256>>>(
        h, e_h, off, eid, Wt, b, norm, out, N);
}

// round 9
// speedup vs baseline: 1.1897x; 1.0016x over previous
#include <cuda_runtime.h>
#include <cstdint>

#define D 128
#define NMAX 50000
#define EMAX 600000
#define MB 64
#define LDP 132
#define BUILD_BLOCKS 296
#define BUILD_T 256

// allocation-free scratch
__device__ int      g_deg[NMAX];
__device__ int      g_off[NMAX + 1];
__device__ int      g_cur[NMAX];
__device__ int      g_eid[EMAX];
__device__ int      g_part[BUILD_BLOCKS];
__device__ uint32_t g_Wt[D * D];      // W as tf32 bits
__device__ unsigned g_bar;            // grid barrier counter (memset to 0 per launch)

__device__ __forceinline__ uint32_t f2tf32(float x) {
    uint32_t r;
    asm("cvt.rna.tf32.f32 %0, %1;" : "=r"(r) : "f"(x));
    return r;
}

// grid-wide barrier: all blocks co-resident (2/SM). target = round * gridDim.x
__device__ __forceinline__ void gridbar(unsigned target) {
    __syncthreads();
    __threadfence();
    if (threadIdx.x == 0) {
        atomicAdd(&g_bar, 1u);
        while (*(volatile unsigned*)&g_bar < target) { }
    }
    __syncthreads();
}

// 256-thread exclusive block scan (shfl warp scans + 8-wide warp-base scan)
__device__ __forceinline__ int block_scan_excl(int v) {
    __shared__ int ws[8];
    int lane = threadIdx.x & 31, w = threadIdx.x >> 5;
    int inc = v;
    #pragma unroll
    for (int o = 1; o < 32; o <<= 1) {
        int u = __shfl_up_sync(0xffffffffu, inc, o);
        if (lane >= o) inc += u;
    }
    if (lane == 31) ws[w] = inc;
    __syncthreads();
    if (w == 0 && lane < 8) {
        int s = ws[lane];
        int si = s;
        #pragma unroll
        for (int o = 1; o < 8; o <<= 1) {
            int u = __shfl_up_sync(0xffu, si, o);
            if (lane >= o) si += u;
        }
        ws[lane] = si - s;
    }
    __syncthreads();
    int r = ws[w] + inc - v;
    __syncthreads();   // protect ws for possible reuse
    return r;
}

// ================= persistent CSR-build kernel (1 launch) ===================
__global__ void __launch_bounds__(BUILD_T)
build_kernel(const int* __restrict__ dst, const float* __restrict__ W,
             int N, int E) {
    const int tid = threadIdx.x;
    const int bid = blockIdx.x;
    const unsigned nb = gridDim.x;
    const int gt = bid * BUILD_T + tid;
    const int stride = nb * BUILD_T;

    // P0: zero deg + convert W to tf32
    for (int i = gt; i < N; i += stride) g_deg[i] = 0;
    for (int i = gt; i < D * D; i += stride) g_Wt[i] = f2tf32(W[i]);
    gridbar(1 * nb);

    // P1: histogram
    for (int e = gt; e < E; e += stride) atomicAdd(&g_deg[__ldg(dst + e)], 1);
    gridbar(2 * nb);

    // P2a: per-chunk partial sums (chunk = 256 consecutive deg entries)
    const int nch = (N + BUILD_T - 1) / BUILD_T;   // 196 <= BUILD_BLOCKS
    const int i = bid * BUILD_T + tid;
    {
        int v = (bid < nch && i < N) ? g_deg[i] : 0;
        // block reduce
        int s = v;
        #pragma unroll
        for (int o = 16; o > 0; o >>= 1) s += __shfl_down_sync(0xffffffffu, s, o);
        __shared__ int red[8];
        if ((tid & 31) == 0) red[tid >> 5] = s;
        __syncthreads();
        if (tid < 8) {
            int t2 = red[tid];
            #pragma unroll
            for (int o = 4; o > 0; o >>= 1) t2 += __shfl_down_sync(0xffu, t2, o);
            if (tid == 0 && bid < nch) g_part[bid] = t2;
        }
        __syncthreads();
    }
    gridbar(3 * nb);

    // P2b: block 0 exclusive-scans the nch partials
    if (bid == 0) {
        int p = (tid < nch) ? g_part[tid] : 0;
        int ex = block_scan_excl(p);
        if (tid < nch) g_part[tid] = ex;
    }
    gridbar(4 * nb);

    // P2c: final offsets
    if (bid < nch) {
        int v = (i < N) ? g_deg[i] : 0;
        int ex = block_scan_excl(v) + g_part[bid];
        if (i < N) {
            g_off[i] = ex;
            g_cur[i] = ex;
            if (i == N - 1) g_off[N] = ex + v;
        }
    }
    gridbar(5 * nb);

    // P3: fill edge-id buckets
    for (int e = gt; e < E; e += stride) {
        int pos = atomicAdd(&g_cur[__ldg(dst + e)], 1);
        g_eid[pos] = e;
    }
}

// ===================== fused gather + TF32 GEMM (R8) ========================
__device__ __forceinline__ void mma_tf32(float* c, const uint32_t* a, const uint32_t* bb) {
    asm volatile(
        "mma.sync.aligned.m16n8k8.row.col.f32.tf32.tf32.f32 "
        "{%0,%1,%2,%3}, {%4,%5,%6,%7}, {%8,%9}, {%0,%1,%2,%3};"
        : "+f"(c[0]), "+f"(c[1]), "+f"(c[2]), "+f"(c[3])
        : "r"(a[0]), "r"(a[1]), "r"(a[2]), "r"(a[3]), "r"(bb[0]), "r"(bb[1]));
}

__global__ void __launch_bounds__(256, 3)
fused_kernel(const float* __restrict__ h,
             const float* __restrict__ e_h,
             const float* __restrict__ b,
             const float* __restrict__ norm,
             float* __restrict__ out,
             int N) {
    __shared__ uint32_t As[MB * LDP];

    const int tid  = threadIdx.x;
    const int wid  = tid >> 5;
    const int lane = tid & 31;
    const int rowBase = blockIdx.x * MB;

    // ---- gather: warp wid handles rows wid*8 .. wid*8+7; 8-deep edge MLP ----
    #pragma unroll 1
    for (int rr = 0; rr < 8; rr++) {
        int r = wid * 8 + rr;
        int n = rowBase + r;
        float4 res = make_float4(0.f, 0.f, 0.f, 0.f);
        if (n < N) {
            int s = __ldg(g_off + n);
            int t = __ldg(g_off + n + 1);
            float4 a0 = make_float4(0.f, 0.f, 0.f, 0.f);
            float4 a1 = make_float4(0.f, 0.f, 0.f, 0.f);
            float4 a2 = make_float4(0.f, 0.f, 0.f, 0.f);
            float4 a3 = make_float4(0.f, 0.f, 0.f, 0.f);
            int i = s;
            for (; i + 7 < t; i += 8) {
                int e0 = __ldg(g_eid + i);
                int e1 = __ldg(g_eid + i + 1);
                int e2 = __ldg(g_eid + i + 2);
                int e3 = __ldg(g_eid + i + 3);
                int e4 = __ldg(g_eid + i + 4);
                int e5 = __ldg(g_eid + i + 5);
                int e6 = __ldg(g_eid + i + 6);
                int e7 = __ldg(g_eid + i + 7);
                float4 v0 = ((const float4*)(e_h + (size_t)e0 * D))[lane];
                float4 v1 = ((const float4*)(e_h + (size_t)e1 * D))[lane];
                float4 v2 = ((const float4*)(e_h + (size_t)e2 * D))[lane];
                float4 v3 = ((const float4*)(e_h + (size_t)e3 * D))[lane];
                float4 v4 = ((const float4*)(e_h + (size_t)e4 * D))[lane];
                float4 v5 = ((const float4*)(e_h + (size_t)e5 * D))[lane];
                float4 v6 = ((const float4*)(e_h + (size_t)e6 * D))[lane];
                float4 v7 = ((const float4*)(e_h + (size_t)e7 * D))[lane];
                a0.x += v0.x; a0.y += v0.y; a0.z += v0.z; a0.w += v0.w;
                a1.x += v1.x; a1.y += v1.y; a1.z += v1.z; a1.w += v1.w;
                a2.x += v2.x; a2.y += v2.y; a2.z += v2.z; a2.w += v2.w;
                a3.x += v3.x; a3.y += v3.y; a3.z += v3.z; a3.w += v3.w;
                a0.x += v4.x; a0.y += v4.y; a0.z += v4.z; a0.w += v4.w;
                a1.x += v5.x; a1.y += v5.y; a1.z += v5.z; a1.w += v5.w;
                a2.x += v6.x; a2.y += v6.y; a2.z += v6.z; a2.w += v6.w;
                a3.x += v7.x; a3.y += v7.y; a3.z += v7.z; a3.w += v7.w;
            }
            for (; i + 3 < t; i += 4) {
                int e0 = __ldg(g_eid + i);
                int e1 = __ldg(g_eid + i + 1);
                int e2 = __ldg(g_eid + i + 2);
                int e3 = __ldg(g_eid + i + 3);
                float4 v0 = ((const float4*)(e_h + (size_t)e0 * D))[lane];
                float4 v1 = ((const float4*)(e_h + (size_t)e1 * D))[lane];
                float4 v2 = ((const float4*)(e_h + (size_t)e2 * D))[lane];
                float4 v3 = ((const float4*)(e_h + (size_t)e3 * D))[lane];
                a0.x += v0.x; a0.y += v0.y; a0.z += v0.z; a0.w += v0.w;
                a1.x += v1.x; a1.y += v1.y; a1.z += v1.z; a1.w += v1.w;
                a2.x += v2.x; a2.y += v2.y; a2.z += v2.z; a2.w += v2.w;
                a3.x += v3.x; a3.y += v3.y; a3.z += v3.z; a3.w += v3.w;
            }
            for (; i < t; i++) {
                int e0 = __ldg(g_eid + i);
                float4 v0 = ((const float4*)(e_h + (size_t)e0 * D))[lane];
                a0.x += v0.x; a0.y += v0.y; a0.z += v0.z; a0.w += v0.w;
            }
            float4 hv = ((const float4*)(h + (size_t)n * D))[lane];
            res.x = (a0.x + a1.x + a2.x + a3.x) * hv.x;
            res.y = (a0.y + a1.y + a2.y + a3.y) * hv.y;
            res.z = (a0.z + a1.z + a2.z + a3.z) * hv.z;
            res.w = (a0.w + a1.w + a2.w + a3.w) * hv.w;
        }
        uint4 tv;
        tv.x = f2tf32(res.x); tv.y = f2tf32(res.y);
        tv.z = f2tf32(res.z); tv.w = f2tf32(res.w);
        *(uint4*)(As + (size_t)r * LDP + lane * 4) = tv;
    }
    __syncthreads();

    // ---- MMA: warp tile 32(M) x 32(N) ----
    const int mBase = (wid & 1) * 32;
    const int nBase = (wid >> 1) * 32;
    const int gID = lane >> 2;
    const int tig = lane & 3;

    float acc[8][4];
    #pragma unroll
    for (int i = 0; i < 8; i++)
        #pragma unroll
        for (int j = 0; j < 4; j++) acc[i][j] = 0.0f;

    #pragma unroll
    for (int ks = 0; ks < 16; ks++) {
        const int k0 = ks * 8;
        uint32_t a[2][4];
        #pragma unroll
        for (int mt = 0; mt < 2; mt++) {
            int r0 = mBase + mt * 16 + gID;
            a[mt][0] = As[(size_t)r0 * LDP + k0 + tig];
            a[mt][1] = As[(size_t)(r0 + 8) * LDP + k0 + tig];
            a[mt][2] = As[(size_t)r0 * LDP + k0 + tig + 4];
            a[mt][3] = As[(size_t)(r0 + 8) * LDP + k0 + tig + 4];
        }
        uint32_t bf[4][2];
        #pragma unroll
        for (int nt = 0; nt < 4; nt++) {
            int nn = nBase + nt * 8 + gID;
            bf[nt][0] = __ldg(g_Wt + (size_t)nn * D + k0 + tig);
            bf[nt][1] = __ldg(g_Wt + (size_t)nn * D + k0 + tig + 4);
        }
        #pragma unroll
        for (int mt = 0; mt < 2; mt++)
            #pragma unroll
            for (int nt = 0; nt < 4; nt++)
                mma_tf32(acc[mt * 4 + nt], a[mt], bf[nt]);
    }

    // ---- epilogue: (acc + b) * norm ----
    #pragma unroll
    for (int mt = 0; mt < 2; mt++) {
        #pragma unroll
        for (int half = 0; half < 2; half++) {
            int m = rowBase + mBase + mt * 16 + half * 8 + gID;
            if (m >= N) continue;
            float nm = __ldg(norm + m);
            #pragma unroll
            for (int nt = 0; nt < 4; nt++) {
                int col = nBase + nt * 8 + tig * 2;
                float2 bb = *(const float2*)(b + col);
                float2 r;
                r.x = (acc[mt * 4 + nt][half * 2 + 0] + bb.x) * nm;
                r.y = (acc[mt * 4 + nt][half * 2 + 1] + bb.y) * nm;
                *(float2*)(out + (size_t)m * D + col) = r;
            }
        }
    }
}

// ============================ launch ========================================
extern "C" void kernel_launch(void* const* d_in, const int* in_sizes, int n_in,
                              void* d_out, int out_size) {
    const float* h    = (const float*)d_in[0];
    const float* e_h  = (const float*)d_in[1];
    const float* norm = (const float*)d_in[2];
    const int*   dst  = (const int*)d_in[3];
    const float* W    = (const float*)d_in[4];
    const float* b    = (const float*)d_in[5];
    float*       out  = (float*)d_out;

    const int N = in_sizes[2];
    const int E = in_sizes[3];

    unsigned* barp = nullptr;
    cudaGetSymbolAddress((void**)&barp, g_bar);
    cudaMemsetAsync(barp, 0, sizeof(unsigned), 0);

    build_kernel<<<BUILD_BLOCKS, BUILD_T>>>(dst, W, N, E);
    fused_kernel<<<(N + MB - 1) / MB, 256>>>(h, e_h, b, norm, out, N);
}